// round 5
// baseline (speedup 1.0000x reference)
#include <cuda_runtime.h>
#include <cuda_bf16.h>
#include <math.h>

// Problem constants
#define QLEN 512
#define RLEN 1024
#define BSZ  8
#define NHEAD 16
#define DHEAD 64
#define DMODEL 1024
#define QB (QLEN*BSZ)          // 4096
#define RB (RLEN*BSZ)          // 8192
#define BN_TOT (BSZ*NHEAD)     // 128
#define IJ (QLEN*QLEN)         // 262144
#define ATT_SCALE 0.125f       // 1/sqrt(64)

// ---------------- scratch (static device globals; no allocation) -------------
__device__ float g_k  [QB*DMODEL];
__device__ float g_v  [QB*DMODEL];
__device__ float g_kr [RB*DMODEL];
__device__ float g_q  [QB*DMODEL];
__device__ float g_av [QB*DMODEL];
__device__ float g_tmp[QB*DMODEL];
__device__ float g_kbw[BN_TOT*QLEN];
__device__ float g_krb[BN_TOT*RLEN];
__device__ float g_e0 [QLEN*BN_TOT];
__device__ float g_e1 [QLEN*BN_TOT];
__device__ float g_S1 [(size_t)BN_TOT*QLEN*QLEN];   // also reused as P
__device__ float g_S2 [(size_t)BN_TOT*QLEN*RLEN];
__device__ float g_maskTh[(size_t)BN_TOT*IJ];
__device__ float g_maskTg[(size_t)BN_TOT*IJ];
__device__ float g_segT[16*IJ];

// ---------------- warp reduction helpers -------------------------------------
__device__ __forceinline__ float warpMax(float v) {
    #pragma unroll
    for (int o = 16; o > 0; o >>= 1) v = fmaxf(v, __shfl_xor_sync(0xffffffffu, v, o));
    return v;
}
__device__ __forceinline__ float warpSum(float v) {
    #pragma unroll
    for (int o = 16; o > 0; o >>= 1) v += __shfl_xor_sync(0xffffffffu, v, o);
    return v;
}

// ---------------- tensor-core plumbing ---------------------------------------
__device__ __forceinline__ unsigned smem_u32(const void* p) {
    return (unsigned)__cvta_generic_to_shared(p);
}
__device__ __forceinline__ void ldm_x4(unsigned addr, unsigned* r) {
    asm volatile("ldmatrix.sync.aligned.m8n8.x4.shared.b16 {%0,%1,%2,%3}, [%4];"
        : "=r"(r[0]), "=r"(r[1]), "=r"(r[2]), "=r"(r[3]) : "r"(addr));
}
__device__ __forceinline__ void ldm_x4_t(unsigned addr, unsigned* r) {
    asm volatile("ldmatrix.sync.aligned.m8n8.x4.trans.shared.b16 {%0,%1,%2,%3}, [%4];"
        : "=r"(r[0]), "=r"(r[1]), "=r"(r[2]), "=r"(r[3]) : "r"(addr));
}
__device__ __forceinline__ void mma_bf16(float* c, const unsigned* a, unsigned b0, unsigned b1) {
    asm volatile("mma.sync.aligned.m16n8k16.row.col.f32.bf16.bf16.f32 "
        "{%0,%1,%2,%3}, {%4,%5,%6,%7}, {%8,%9}, {%0,%1,%2,%3};"
        : "+f"(c[0]), "+f"(c[1]), "+f"(c[2]), "+f"(c[3])
        : "r"(a[0]), "r"(a[1]), "r"(a[2]), "r"(a[3]), "r"(b0), "r"(b1));
}
__device__ __forceinline__ void split_store4(float4 v, unsigned short* hi, unsigned short* lo) {
    float vv[4] = {v.x, v.y, v.z, v.w};
    #pragma unroll
    for (int j = 0; j < 4; ++j) {
        __nv_bfloat16 hb = __float2bfloat16(vv[j]);
        float res = vv[j] - __bfloat162float(hb);
        hi[j] = __bfloat16_as_ushort(hb);
        lo[j] = __bfloat16_as_ushort(__float2bfloat16(res));
    }
}

// Split-bf16 tensor GEMM, NN: C = A(MxK) * B(KxN), all fp32 row-major.
// BM=128, BN=64, BK=32, 256 threads (8 warps, each 32x32).
// C += Ah*Bh + Ah*Bl + Al*Bh  (3-pass split precision, rel err ~1e-5).
#define LDA_S 40   // A smem row stride (bf16 elems), 80 B, ldmatrix conflict-free
#define LDBNN_S 72 // B smem row stride NN, 144 B
#define LDBNT_S 40 // B smem row stride NT, 80 B

__global__ void __launch_bounds__(256, 2)
tmma_nn(const float* __restrict__ A, const float* __restrict__ B,
        float* __restrict__ C,
        int K, int lda, int ldb, int ldc,
        long long sA, long long sB, long long sC)
{
    __shared__ unsigned short Ah[128*LDA_S], Al[128*LDA_S];
    __shared__ unsigned short Bh[32*LDBNN_S], Bl[32*LDBNN_S];
    const int bz = blockIdx.z;
    A += (size_t)bz * sA; B += (size_t)bz * sB; C += (size_t)bz * sC;
    const int m0 = blockIdx.y * 128, n0 = blockIdx.x * 64;
    const int tid = threadIdx.x, warp = tid >> 5, lane = tid & 31;
    const int wm = (warp >> 1) * 32, wn = (warp & 1) * 32;
    const unsigned baseAh = smem_u32(Ah), baseAl = smem_u32(Al);
    const unsigned baseBh = smem_u32(Bh), baseBl = smem_u32(Bl);

    float c[2][2][2][4];
    #pragma unroll
    for (int a = 0; a < 2; ++a)
        #pragma unroll
        for (int b = 0; b < 2; ++b)
            #pragma unroll
            for (int s = 0; s < 2; ++s)
                #pragma unroll
                for (int q = 0; q < 4; ++q) c[a][b][s][q] = 0.f;

    for (int kt = 0; kt < K; kt += 32) {
        {   // A tile 128x32: thread -> row tid/2, 4 float4 at f4 (tid&1)*4+i
            int r = tid >> 1;
            const float4* src = (const float4*)(A + (size_t)(m0 + r) * lda + kt) + (tid & 1) * 4;
            unsigned short* ah = &Ah[r * LDA_S + (tid & 1) * 16];
            unsigned short* al = &Al[r * LDA_S + (tid & 1) * 16];
            #pragma unroll
            for (int i = 0; i < 4; ++i) split_store4(src[i], ah + i * 4, al + i * 4);
        }
        {   // B tile 32x64: thread -> row tid/8, 2 float4 at f4 (tid&7)*2+i
            int r = tid >> 3;
            const float4* src = (const float4*)(B + (size_t)(kt + r) * ldb + n0) + (tid & 7) * 2;
            unsigned short* bh = &Bh[r * LDBNN_S + (tid & 7) * 8];
            unsigned short* bl = &Bl[r * LDBNN_S + (tid & 7) * 8];
            #pragma unroll
            for (int i = 0; i < 2; ++i) split_store4(src[i], bh + i * 4, bl + i * 4);
        }
        __syncthreads();
        #pragma unroll
        for (int ks = 0; ks < 2; ++ks) {
            unsigned ah[2][4], al_[2][4];
            #pragma unroll
            for (int mt = 0; mt < 2; ++mt) {
                unsigned off = (unsigned)((wm + mt * 16 + (lane & 15)) * (LDA_S * 2)
                               + ks * 32 + (lane >> 4) * 16);
                ldm_x4(baseAh + off, ah[mt]);
                ldm_x4(baseAl + off, al_[mt]);
            }
            unsigned bh[2][4], bl_[2][4];
            #pragma unroll
            for (int np = 0; np < 2; ++np) {
                unsigned off = (unsigned)((ks * 16 + (lane & 15)) * (LDBNN_S * 2)
                               + (wn + np * 16 + (lane >> 4) * 8) * 2);
                ldm_x4_t(baseBh + off, bh[np]);
                ldm_x4_t(baseBl + off, bl_[np]);
            }
            #pragma unroll
            for (int mt = 0; mt < 2; ++mt)
                #pragma unroll
                for (int np = 0; np < 2; ++np) {
                    mma_bf16(c[mt][np][0], ah[mt],  bh[np][0],  bh[np][1]);
                    mma_bf16(c[mt][np][1], ah[mt],  bh[np][2],  bh[np][3]);
                    mma_bf16(c[mt][np][0], ah[mt],  bl_[np][0], bl_[np][1]);
                    mma_bf16(c[mt][np][1], ah[mt],  bl_[np][2], bl_[np][3]);
                    mma_bf16(c[mt][np][0], al_[mt], bh[np][0],  bh[np][1]);
                    mma_bf16(c[mt][np][1], al_[mt], bh[np][2],  bh[np][3]);
                }
        }
        __syncthreads();
    }
    const int gq = lane >> 2, tq = lane & 3;
    #pragma unroll
    for (int mt = 0; mt < 2; ++mt)
        #pragma unroll
        for (int np = 0; np < 2; ++np)
            #pragma unroll
            for (int sub = 0; sub < 2; ++sub) {
                int row = m0 + wm + mt * 16 + gq;
                int col = n0 + wn + np * 16 + sub * 8 + tq * 2;
                float* cp = C + (size_t)row * ldc + col;
                *(float2*)cp = make_float2(c[mt][np][sub][0], c[mt][np][sub][1]);
                *(float2*)(cp + (size_t)8 * ldc) = make_float2(c[mt][np][sub][2], c[mt][np][sub][3]);
            }
}

// Split-bf16 tensor GEMM, NT: C = A(MxK) * B(NxK)^T.
__global__ void __launch_bounds__(256, 2)
tmma_nt(const float* __restrict__ A, const float* __restrict__ B,
        float* __restrict__ C,
        int K, int lda, int ldb, int ldc,
        long long sA, long long sB, long long sC)
{
    __shared__ unsigned short Ah[128*LDA_S], Al[128*LDA_S];
    __shared__ unsigned short Bh[64*LDBNT_S], Bl[64*LDBNT_S];
    const int bz = blockIdx.z;
    A += (size_t)bz * sA; B += (size_t)bz * sB; C += (size_t)bz * sC;
    const int m0 = blockIdx.y * 128, n0 = blockIdx.x * 64;
    const int tid = threadIdx.x, warp = tid >> 5, lane = tid & 31;
    const int wm = (warp >> 1) * 32, wn = (warp & 1) * 32;
    const unsigned baseAh = smem_u32(Ah), baseAl = smem_u32(Al);
    const unsigned baseBh = smem_u32(Bh), baseBl = smem_u32(Bl);

    float c[2][2][2][4];
    #pragma unroll
    for (int a = 0; a < 2; ++a)
        #pragma unroll
        for (int b = 0; b < 2; ++b)
            #pragma unroll
            for (int s = 0; s < 2; ++s)
                #pragma unroll
                for (int q = 0; q < 4; ++q) c[a][b][s][q] = 0.f;

    for (int kt = 0; kt < K; kt += 32) {
        {   // A tile 128x32
            int r = tid >> 1;
            const float4* src = (const float4*)(A + (size_t)(m0 + r) * lda + kt) + (tid & 1) * 4;
            unsigned short* ah = &Ah[r * LDA_S + (tid & 1) * 16];
            unsigned short* al = &Al[r * LDA_S + (tid & 1) * 16];
            #pragma unroll
            for (int i = 0; i < 4; ++i) split_store4(src[i], ah + i * 4, al + i * 4);
        }
        {   // B tile 64(n) x 32(k): thread -> row tid/4, 2 float4 at f4 (tid&3)*2+i
            int r = tid >> 2;
            const float4* src = (const float4*)(B + (size_t)(n0 + r) * ldb + kt) + (tid & 3) * 2;
            unsigned short* bh = &Bh[r * LDBNT_S + (tid & 3) * 8];
            unsigned short* bl = &Bl[r * LDBNT_S + (tid & 3) * 8];
            #pragma unroll
            for (int i = 0; i < 2; ++i) split_store4(src[i], bh + i * 4, bl + i * 4);
        }
        __syncthreads();
        #pragma unroll
        for (int ks = 0; ks < 2; ++ks) {
            unsigned ah[2][4], al_[2][4];
            #pragma unroll
            for (int mt = 0; mt < 2; ++mt) {
                unsigned off = (unsigned)((wm + mt * 16 + (lane & 15)) * (LDA_S * 2)
                               + ks * 32 + (lane >> 4) * 16);
                ldm_x4(baseAh + off, ah[mt]);
                ldm_x4(baseAl + off, al_[mt]);
            }
            // B fragments: A-style ldmatrix on [n][k] tile.
            // r0=(n0-7,k0-7) r1=(n8-15,k0-7) r2=(n0-7,k8-15) r3=(n8-15,k8-15)
            unsigned bh[2][4], bl_[2][4];
            #pragma unroll
            for (int np = 0; np < 2; ++np) {
                unsigned off = (unsigned)((wn + np * 16 + (lane & 15)) * (LDBNT_S * 2)
                               + ks * 32 + (lane >> 4) * 16);
                ldm_x4(baseBh + off, bh[np]);
                ldm_x4(baseBl + off, bl_[np]);
            }
            #pragma unroll
            for (int mt = 0; mt < 2; ++mt)
                #pragma unroll
                for (int np = 0; np < 2; ++np) {
                    mma_bf16(c[mt][np][0], ah[mt],  bh[np][0],  bh[np][2]);
                    mma_bf16(c[mt][np][1], ah[mt],  bh[np][1],  bh[np][3]);
                    mma_bf16(c[mt][np][0], ah[mt],  bl_[np][0], bl_[np][2]);
                    mma_bf16(c[mt][np][1], ah[mt],  bl_[np][1], bl_[np][3]);
                    mma_bf16(c[mt][np][0], al_[mt], bh[np][0],  bh[np][2]);
                    mma_bf16(c[mt][np][1], al_[mt], bh[np][1],  bh[np][3]);
                }
        }
        __syncthreads();
    }
    const int gq = lane >> 2, tq = lane & 3;
    #pragma unroll
    for (int mt = 0; mt < 2; ++mt)
        #pragma unroll
        for (int np = 0; np < 2; ++np)
            #pragma unroll
            for (int sub = 0; sub < 2; ++sub) {
                int row = m0 + wm + mt * 16 + gq;
                int col = n0 + wn + np * 16 + sub * 8 + tq * 2;
                float* cp = C + (size_t)row * ldc + col;
                *(float2*)cp = make_float2(c[mt][np][sub][0], c[mt][np][sub][1]);
                *(float2*)(cp + (size_t)8 * ldc) = make_float2(c[mt][np][sub][2], c[mt][np][sub][3]);
            }
}

// ---------------- 2D transpose: in[R][C] -> out[C][R] -----------------------
__global__ void transpose2d(const float* __restrict__ in, float* __restrict__ out,
                            int R, int C)
{
    __shared__ float tile[32][33];
    const int c0 = blockIdx.x * 32, r0 = blockIdx.y * 32;
    for (int rr = threadIdx.y; rr < 32; rr += 8) {
        int r = r0 + rr, c = c0 + threadIdx.x;
        if (r < R && c < C) tile[rr][threadIdx.x] = in[(size_t)r * C + c];
    }
    __syncthreads();
    for (int cc = threadIdx.y; cc < 32; cc += 8) {
        int oc = c0 + cc, orw = r0 + threadIdx.x;
        if (oc < C && orw < R) out[(size_t)oc * R + orw] = tile[threadIdx.x][cc];
    }
}

// ---------------- kbw / krb: out[bn*J + j] = bias[n] . vecs[j,b,n,:] ---------
__global__ void bias_dot(const float* __restrict__ vecs, const float* __restrict__ bias,
                         float* __restrict__ out, int J)
{
    int idx = blockIdx.x * blockDim.x + threadIdx.x;
    if (idx >= BN_TOT * J) return;
    int bn = idx / J, j = idx - bn * J;
    int n = bn & 15;
    const float4* v = (const float4*)(vecs + ((size_t)j * BN_TOT + bn) * DHEAD);
    const float4* bp = (const float4*)(bias + n * DHEAD);
    float acc = 0.f;
    #pragma unroll
    for (int d = 0; d < 16; ++d) {
        float4 a = v[d], b = bp[d];
        acc += a.x*b.x + a.y*b.y + a.z*b.z + a.w*b.w;
    }
    out[idx] = acc;
}

// ---------------- efq[i,b,n,s] = (q+r_s_bias) . seg_embed[s,n,:] -------------
__global__ void compute_efq(const float* __restrict__ q, const float* __restrict__ rsb,
                            const float* __restrict__ se,
                            float* __restrict__ e0, float* __restrict__ e1)
{
    int idx = blockIdx.x * blockDim.x + threadIdx.x;   // (i*8+b)*16+n, 65536 total
    if (idx >= QLEN * BN_TOT) return;
    int n = idx & 15;
    const float* qp = q + (size_t)idx * DHEAD;
    const float* rb = rsb + n * DHEAD;
    const float* s0 = se + n * DHEAD;
    const float* s1 = se + (16 + n) * DHEAD;
    float a0 = 0.f, a1 = 0.f;
    #pragma unroll
    for (int d = 0; d < DHEAD; ++d) {
        float qv = qp[d] + rb[d];
        a0 += qv * s0[d];
        a1 += qv * s1[d];
    }
    e0[idx] = a0; e1[idx] = a1;
}

// ---------------- combine scores + softmax; writes P in place over S1 -------
__global__ void __launch_bounds__(256, 4)
combine_softmax(float* __restrict__ S1, const float* __restrict__ S2,
                const float* __restrict__ kbw, const float* __restrict__ krb,
                const float* __restrict__ e0a, const float* __restrict__ e1a,
                const float* __restrict__ maskT, const float* __restrict__ segT)
{
    const int i = blockIdx.x, bn = blockIdx.y, b = bn >> 4;
    const int tid = threadIdx.x;                 // 256 threads, 2 j each
    float* s1row = S1 + ((size_t)bn * QLEN + i) * QLEN;
    const float* s2row = S2 + ((size_t)bn * QLEN + i) * RLEN;
    const float* mrow  = maskT + (size_t)bn * IJ + (size_t)i * QLEN;
    const float* sg0   = segT + (size_t)(b * 2) * IJ + (size_t)i * QLEN;
    const float* sg1   = sg0 + IJ;
    const float* kb = kbw + bn * QLEN;
    const float* kr = krb + bn * RLEN;
    const float e0 = e0a[i * BN_TOT + bn], e1 = e1a[i * BN_TOT + bn];

    float sc[2];
    #pragma unroll
    for (int t = 0; t < 2; ++t) {
        int j = tid + t * 256;
        int p = QLEN - i + j;                    // rel_shift gather, in [1,1023]
        float v = s1row[j] + s2row[p] + kb[j] + kr[p] + sg0[j] * e0 + sg1[j] * e1;
        sc[t] = v * ATT_SCALE - 1e30f * mrow[j];
    }

    const int lane = tid & 31, wid = tid >> 5;
    __shared__ float sred[8];

    float mx = warpMax(fmaxf(sc[0], sc[1]));
    if (lane == 0) sred[wid] = mx;
    __syncthreads();
    if (wid == 0) {
        float v = (lane < 8) ? sred[lane] : -3.0e38f;
        v = warpMax(v);
        if (lane == 0) sred[0] = v;
    }
    __syncthreads();
    mx = sred[0];
    __syncthreads();

    float ex0 = expf(sc[0] - mx), ex1 = expf(sc[1] - mx);
    float s = warpSum(ex0 + ex1);
    if (lane == 0) sred[wid] = s;
    __syncthreads();
    if (wid == 0) {
        float v = (lane < 8) ? sred[lane] : 0.f;
        v = warpSum(v);
        if (lane == 0) sred[0] = v;
    }
    __syncthreads();
    float inv = 1.f / sred[0];
    s1row[tid]       = ex0 * inv;
    s1row[tid + 256] = ex1 * inv;
}

// ---------------- residual + LayerNorm over last dim (1024) ------------------
__global__ void __launch_bounds__(256, 4)
residual_ln(const float* __restrict__ proj, const float* __restrict__ res,
            const float* __restrict__ gamma, const float* __restrict__ beta,
            float* __restrict__ out)
{
    const int row = blockIdx.x;                  // 4096 rows
    const int tid = threadIdx.x;                 // 256 threads, 4 cols each
    const float* p = proj + (size_t)row * DMODEL;
    const float* r = res  + (size_t)row * DMODEL;
    float x[4];
    float s = 0.f;
    #pragma unroll
    for (int c = 0; c < 4; ++c) {
        int col = tid + c * 256;
        x[c] = p[col] + r[col];
        s += x[c];
    }
    const int lane = tid & 31, wid = tid >> 5;
    __shared__ float sred[8];
    s = warpSum(s);
    if (lane == 0) sred[wid] = s;
    __syncthreads();
    if (wid == 0) {
        float v = (lane < 8) ? sred[lane] : 0.f;
        v = warpSum(v);
        if (lane == 0) sred[0] = v;
    }
    __syncthreads();
    const float mu = sred[0] * (1.f / DMODEL);
    __syncthreads();
    float vs = 0.f;
    #pragma unroll
    for (int c = 0; c < 4; ++c) { float d = x[c] - mu; vs += d * d; }
    vs = warpSum(vs);
    if (lane == 0) sred[wid] = vs;
    __syncthreads();
    if (wid == 0) {
        float v = (lane < 8) ? sred[lane] : 0.f;
        v = warpSum(v);
        if (lane == 0) sred[0] = v;
    }
    __syncthreads();
    const float rs = rsqrtf(sred[0] * (1.f / DMODEL) + 1e-12f);
    float* o = out + (size_t)row * DMODEL;
    #pragma unroll
    for (int c = 0; c < 4; ++c) {
        int col = tid + c * 256;
        o[col] = (x[c] - mu) * rs * gamma[col] + beta[col];
    }
}

// ---------------- launch --------------------------------------------------
extern "C" void kernel_launch(void* const* d_in, const int* in_sizes, int n_in,
                              void* d_out, int out_size)
{
    const float* h       = (const float*)d_in[0];
    const float* g       = (const float*)d_in[1];
    const float* r       = (const float*)d_in[2];
    const float* mask_h  = (const float*)d_in[3];
    const float* mask_g  = (const float*)d_in[4];
    const float* seg_mat = (const float*)d_in[5];
    const float* wq      = (const float*)d_in[6];
    const float* wk      = (const float*)d_in[7];
    const float* wv      = (const float*)d_in[8];
    const float* wo      = (const float*)d_in[9];
    const float* wr      = (const float*)d_in[10];
    const float* rwb     = (const float*)d_in[11];
    const float* rrb     = (const float*)d_in[12];
    const float* rsb     = (const float*)d_in[13];
    const float* se      = (const float*)d_in[14];
    const float* gamma   = (const float*)d_in[15];
    const float* beta    = (const float*)d_in[16];
    float* out = (float*)d_out;

    float *pk, *pv, *pkr, *pq, *pav, *ptmp, *pkbw, *pkrb, *pe0, *pe1,
          *pS1, *pS2, *pmTh, *pmTg, *psegT;
    cudaGetSymbolAddress((void**)&pk,   g_k);
    cudaGetSymbolAddress((void**)&pv,   g_v);
    cudaGetSymbolAddress((void**)&pkr,  g_kr);
    cudaGetSymbolAddress((void**)&pq,   g_q);
    cudaGetSymbolAddress((void**)&pav,  g_av);
    cudaGetSymbolAddress((void**)&ptmp, g_tmp);
    cudaGetSymbolAddress((void**)&pkbw, g_kbw);
    cudaGetSymbolAddress((void**)&pkrb, g_krb);
    cudaGetSymbolAddress((void**)&pe0,  g_e0);
    cudaGetSymbolAddress((void**)&pe1,  g_e1);
    cudaGetSymbolAddress((void**)&pS1,  g_S1);
    cudaGetSymbolAddress((void**)&pS2,  g_S2);
    cudaGetSymbolAddress((void**)&pmTh, g_maskTh);
    cudaGetSymbolAddress((void**)&pmTg, g_maskTg);
    cudaGetSymbolAddress((void**)&psegT, g_segT);

    // ---- shared precompute ----
    // K, V projections: [4096,1024] = h[4096,1024] @ w[1024,1024]
    tmma_nn<<<dim3(16, 32, 1), 256>>>(h, wk, pk, DMODEL, DMODEL, DMODEL, DMODEL, 0, 0, 0);
    tmma_nn<<<dim3(16, 32, 1), 256>>>(h, wv, pv, DMODEL, DMODEL, DMODEL, DMODEL, 0, 0, 0);
    // Kr projection: [8192,1024]
    tmma_nn<<<dim3(16, 64, 1), 256>>>(r, wr, pkr, DMODEL, DMODEL, DMODEL, DMODEL, 0, 0, 0);
    // bias . key dot products
    bias_dot<<<(BN_TOT * QLEN + 255) / 256, 256>>>(pk,  rwb, pkbw, QLEN);
    bias_dot<<<(BN_TOT * RLEN + 255) / 256, 256>>>(pkr, rrb, pkrb, RLEN);
    // transposes: [ij, bn] -> [bn, ij]
    transpose2d<<<dim3(4, IJ / 32), dim3(32, 8)>>>(mask_h,  pmTh, IJ, BN_TOT);
    transpose2d<<<dim3(4, IJ / 32), dim3(32, 8)>>>(mask_g,  pmTg, IJ, BN_TOT);
    transpose2d<<<dim3(1, IJ / 32), dim3(32, 8)>>>(seg_mat, psegT, IJ, 16);

    // ---- per-stream pipeline ----
    for (int stream = 0; stream < 2; ++stream) {
        const float* x = stream == 0 ? h : g;
        const float* mT = stream == 0 ? pmTh : pmTg;
        float* dst = out + (size_t)stream * QB * DMODEL;

        // Q projection
        tmma_nn<<<dim3(16, 32, 1), 256>>>(x, wq, pq, DMODEL, DMODEL, DMODEL, DMODEL, 0, 0, 0);
        // segment-term dot products
        compute_efq<<<(QLEN * BN_TOT + 255) / 256, 256>>>(pq, rsb, se, pe0, pe1);
        // S1[bn,i,j] = Q . K^T   (batched over bn)
        tmma_nt<<<dim3(8, 4, BN_TOT), 256>>>(pq, pk, pS1, DHEAD,
                                             BN_TOT * DHEAD, BN_TOT * DHEAD, QLEN,
                                             DHEAD, DHEAD, (long long)QLEN * QLEN);
        // S2[bn,i,p] = Q . Kr^T
        tmma_nt<<<dim3(16, 4, BN_TOT), 256>>>(pq, pkr, pS2, DHEAD,
                                              BN_TOT * DHEAD, BN_TOT * DHEAD, RLEN,
                                              DHEAD, DHEAD, (long long)QLEN * RLEN);
        // scores + rel-shift gather + seg + mask + softmax -> P (in S1)
        combine_softmax<<<dim3(QLEN, BN_TOT), 256>>>(pS1, pS2, pkbw, pkrb, pe0, pe1, mT, psegT);
        // attn_vec[i,b,n,d] = P . V  (batched over bn)
        tmma_nn<<<dim3(1, 4, BN_TOT), 256>>>(pS1, pv, pav, QLEN,
                                             QLEN, BN_TOT * DHEAD, BN_TOT * DHEAD,
                                             (long long)QLEN * QLEN, DHEAD, DHEAD);
        // output projection: [4096,1024] @ wo[1024,1024]^T
        tmma_nt<<<dim3(16, 32, 1), 256>>>(pav, wo, ptmp, DMODEL, DMODEL, DMODEL, DMODEL, 0, 0, 0);
        // residual + LayerNorm -> d_out
        residual_ln<<<QB, 256>>>(ptmp, x, gamma, beta, dst);
    }
    (void)in_sizes; (void)n_in; (void)out_size;
}

// round 6
// speedup vs baseline: 2.2246x; 2.2246x over previous
#include <cuda_runtime.h>
#include <cuda_bf16.h>
#include <math.h>

// Problem constants
#define QLEN 512
#define RLEN 1024
#define BSZ  8
#define NHEAD 16
#define DHEAD 64
#define DMODEL 1024
#define QB (QLEN*BSZ)          // 4096
#define RB (RLEN*BSZ)          // 8192
#define BN_TOT (BSZ*NHEAD)     // 128
#define IJ (QLEN*QLEN)         // 262144
#define ATT_SCALE 0.125f       // 1/sqrt(64)

typedef unsigned short ushort_t;

// ---------------- fp32 scratch ------------------------------------------------
__device__ float g_k  [QB*DMODEL];
__device__ float g_v  [QB*DMODEL];
__device__ float g_kr [RB*DMODEL];
__device__ float g_q  [QB*DMODEL];
__device__ float g_av [QB*DMODEL];
__device__ float g_tmp[QB*DMODEL];
__device__ float g_kbw[BN_TOT*QLEN];
__device__ float g_krb[BN_TOT*RLEN];
__device__ float g_e0 [QLEN*BN_TOT];
__device__ float g_e1 [QLEN*BN_TOT];
__device__ float g_S1 [(size_t)BN_TOT*QLEN*QLEN];
__device__ float g_S2 [(size_t)BN_TOT*QLEN*RLEN];
__device__ float g_maskTh[(size_t)BN_TOT*IJ];
__device__ float g_maskTg[(size_t)BN_TOT*IJ];
__device__ float g_segT[16*IJ];

// ---------------- split-bf16 (hi/lo) scratch ---------------------------------
__device__ ushort_t g_hH[QB*DMODEL],  g_hL[QB*DMODEL];
__device__ ushort_t g_gH[QB*DMODEL],  g_gL[QB*DMODEL];
__device__ ushort_t g_rH[RB*DMODEL],  g_rL[RB*DMODEL];
__device__ ushort_t g_wqH[DMODEL*DMODEL], g_wqL[DMODEL*DMODEL];
__device__ ushort_t g_wkH[DMODEL*DMODEL], g_wkL[DMODEL*DMODEL];
__device__ ushort_t g_wvH[DMODEL*DMODEL], g_wvL[DMODEL*DMODEL];
__device__ ushort_t g_woH[DMODEL*DMODEL], g_woL[DMODEL*DMODEL];
__device__ ushort_t g_wrH[DMODEL*DMODEL], g_wrL[DMODEL*DMODEL];
__device__ ushort_t g_qH[QB*DMODEL],  g_qL[QB*DMODEL];
__device__ ushort_t g_kH[QB*DMODEL],  g_kL[QB*DMODEL];
__device__ ushort_t g_vH[QB*DMODEL],  g_vL[QB*DMODEL];
__device__ ushort_t g_krH[RB*DMODEL], g_krL[RB*DMODEL];
__device__ ushort_t g_PH[(size_t)BN_TOT*IJ], g_PL[(size_t)BN_TOT*IJ];
__device__ ushort_t g_avH[QB*DMODEL], g_avL[QB*DMODEL];

// ---------------- warp reduction helpers -------------------------------------
__device__ __forceinline__ float warpMax(float v) {
    #pragma unroll
    for (int o = 16; o > 0; o >>= 1) v = fmaxf(v, __shfl_xor_sync(0xffffffffu, v, o));
    return v;
}
__device__ __forceinline__ float warpSum(float v) {
    #pragma unroll
    for (int o = 16; o > 0; o >>= 1) v += __shfl_xor_sync(0xffffffffu, v, o);
    return v;
}

// ---------------- tensor-core plumbing ---------------------------------------
__device__ __forceinline__ unsigned smem_u32(const void* p) {
    return (unsigned)__cvta_generic_to_shared(p);
}
__device__ __forceinline__ void ldm_x4(unsigned addr, unsigned* r) {
    asm volatile("ldmatrix.sync.aligned.m8n8.x4.shared.b16 {%0,%1,%2,%3}, [%4];"
        : "=r"(r[0]), "=r"(r[1]), "=r"(r[2]), "=r"(r[3]) : "r"(addr));
}
__device__ __forceinline__ void ldm_x4_t(unsigned addr, unsigned* r) {
    asm volatile("ldmatrix.sync.aligned.m8n8.x4.trans.shared.b16 {%0,%1,%2,%3}, [%4];"
        : "=r"(r[0]), "=r"(r[1]), "=r"(r[2]), "=r"(r[3]) : "r"(addr));
}
__device__ __forceinline__ void mma_bf16(float* c, const unsigned* a, unsigned b0, unsigned b1) {
    asm volatile("mma.sync.aligned.m16n8k16.row.col.f32.bf16.bf16.f32 "
        "{%0,%1,%2,%3}, {%4,%5,%6,%7}, {%8,%9}, {%0,%1,%2,%3};"
        : "+f"(c[0]), "+f"(c[1]), "+f"(c[2]), "+f"(c[3])
        : "r"(a[0]), "r"(a[1]), "r"(a[2]), "r"(a[3]), "r"(b0), "r"(b1));
}
__device__ __forceinline__ void split1(float v, ushort_t& hi, ushort_t& lo) {
    __nv_bfloat16 hb = __float2bfloat16(v);
    hi = __bfloat16_as_ushort(hb);
    lo = __bfloat16_as_ushort(__float2bfloat16(v - __bfloat162float(hb)));
}

// ---------------- one-shot fp32 -> (hi, lo) bf16 converter -------------------
__global__ void cvt_split(const float* __restrict__ in,
                          ushort_t* __restrict__ hi, ushort_t* __restrict__ lo, int n4)
{
    int i = blockIdx.x * blockDim.x + threadIdx.x;
    if (i >= n4) return;
    float4 v = ((const float4*)in)[i];
    ushort_t h[4], l[4];
    split1(v.x, h[0], l[0]); split1(v.y, h[1], l[1]);
    split1(v.z, h[2], l[2]); split1(v.w, h[3], l[3]);
    ((uint2*)hi)[i] = *(uint2*)h;
    ((uint2*)lo)[i] = *(uint2*)l;
}

// Split-bf16 tensor GEMM, NN: C = Aop(MxK) * Bop(KxN); operands pre-split.
// BM=128, BN=64, BK=32, 256 threads (8 warps, each 32x32).
// C += Ah*Bh + Ah*Bl + Al*Bh  (3-pass split precision).
#define LDA_S 40   // A smem row stride (bf16 elems), 80 B
#define LDBNN_S 72 // B smem row stride NN, 144 B
#define LDBNT_S 40 // B smem row stride NT, 80 B

__global__ void __launch_bounds__(256, 2)
tmma_nn(const ushort_t* __restrict__ AH, const ushort_t* __restrict__ AL,
        const ushort_t* __restrict__ BH, const ushort_t* __restrict__ BL,
        float* __restrict__ C,
        int K, int lda, int ldb, int ldc,
        long long sA, long long sB, long long sC)
{
    __shared__ ushort_t Ah[128*LDA_S], Al[128*LDA_S];
    __shared__ ushort_t Bh[32*LDBNN_S], Bl[32*LDBNN_S];
    const int bz = blockIdx.z;
    AH += (size_t)bz * sA; AL += (size_t)bz * sA;
    BH += (size_t)bz * sB; BL += (size_t)bz * sB;
    C  += (size_t)bz * sC;
    const int m0 = blockIdx.y * 128, n0 = blockIdx.x * 64;
    const int tid = threadIdx.x, warp = tid >> 5, lane = tid & 31;
    const int wm = (warp >> 1) * 32, wn = (warp & 1) * 32;
    const unsigned baseAh = smem_u32(Ah), baseAl = smem_u32(Al);
    const unsigned baseBh = smem_u32(Bh), baseBl = smem_u32(Bl);

    float c[2][2][2][4];
    #pragma unroll
    for (int a = 0; a < 2; ++a)
        #pragma unroll
        for (int b = 0; b < 2; ++b)
            #pragma unroll
            for (int s = 0; s < 2; ++s)
                #pragma unroll
                for (int q = 0; q < 4; ++q) c[a][b][s][q] = 0.f;

    const int ar = tid >> 1, ac = (tid & 1) * 16;       // A: row, col(ushort)
    const int br = tid >> 3, bc = (tid & 7) * 8;        // B: row, col(ushort)

    for (int kt = 0; kt < K; kt += 32) {
        {   // A tile 128x32 ushorts: 2 uint4 per thread from each of hi/lo
            size_t go = (size_t)(m0 + ar) * lda + kt + ac;
            *(uint4*)&Ah[ar * LDA_S + ac]     = *(const uint4*)(AH + go);
            *(uint4*)&Ah[ar * LDA_S + ac + 8] = *(const uint4*)(AH + go + 8);
            *(uint4*)&Al[ar * LDA_S + ac]     = *(const uint4*)(AL + go);
            *(uint4*)&Al[ar * LDA_S + ac + 8] = *(const uint4*)(AL + go + 8);
        }
        {   // B tile 32x64 ushorts: 1 uint4 per thread from each of hi/lo
            size_t go = (size_t)(kt + br) * ldb + n0 + bc;
            *(uint4*)&Bh[br * LDBNN_S + bc] = *(const uint4*)(BH + go);
            *(uint4*)&Bl[br * LDBNN_S + bc] = *(const uint4*)(BL + go);
        }
        __syncthreads();
        #pragma unroll
        for (int ks = 0; ks < 2; ++ks) {
            unsigned ah[2][4], al_[2][4];
            #pragma unroll
            for (int mt = 0; mt < 2; ++mt) {
                unsigned off = (unsigned)((wm + mt * 16 + (lane & 15)) * (LDA_S * 2)
                               + ks * 32 + (lane >> 4) * 16);
                ldm_x4(baseAh + off, ah[mt]);
                ldm_x4(baseAl + off, al_[mt]);
            }
            unsigned bh[2][4], bl_[2][4];
            #pragma unroll
            for (int np = 0; np < 2; ++np) {
                unsigned off = (unsigned)((ks * 16 + (lane & 15)) * (LDBNN_S * 2)
                               + (wn + np * 16 + (lane >> 4) * 8) * 2);
                ldm_x4_t(baseBh + off, bh[np]);
                ldm_x4_t(baseBl + off, bl_[np]);
            }
            #pragma unroll
            for (int mt = 0; mt < 2; ++mt)
                #pragma unroll
                for (int np = 0; np < 2; ++np) {
                    mma_bf16(c[mt][np][0], ah[mt],  bh[np][0],  bh[np][1]);
                    mma_bf16(c[mt][np][1], ah[mt],  bh[np][2],  bh[np][3]);
                    mma_bf16(c[mt][np][0], ah[mt],  bl_[np][0], bl_[np][1]);
                    mma_bf16(c[mt][np][1], ah[mt],  bl_[np][2], bl_[np][3]);
                    mma_bf16(c[mt][np][0], al_[mt], bh[np][0],  bh[np][1]);
                    mma_bf16(c[mt][np][1], al_[mt], bh[np][2],  bh[np][3]);
                }
        }
        __syncthreads();
    }
    const int gq = lane >> 2, tq = lane & 3;
    #pragma unroll
    for (int mt = 0; mt < 2; ++mt)
        #pragma unroll
        for (int np = 0; np < 2; ++np)
            #pragma unroll
            for (int sub = 0; sub < 2; ++sub) {
                int row = m0 + wm + mt * 16 + gq;
                int col = n0 + wn + np * 16 + sub * 8 + tq * 2;
                float* cp = C + (size_t)row * ldc + col;
                *(float2*)cp = make_float2(c[mt][np][sub][0], c[mt][np][sub][1]);
                *(float2*)(cp + (size_t)8 * ldc) = make_float2(c[mt][np][sub][2], c[mt][np][sub][3]);
            }
}

// Split-bf16 tensor GEMM, NT: C = Aop(MxK) * Bop(NxK)^T; operands pre-split.
__global__ void __launch_bounds__(256, 2)
tmma_nt(const ushort_t* __restrict__ AH, const ushort_t* __restrict__ AL,
        const ushort_t* __restrict__ BH, const ushort_t* __restrict__ BL,
        float* __restrict__ C,
        int K, int lda, int ldb, int ldc,
        long long sA, long long sB, long long sC)
{
    __shared__ ushort_t Ah[128*LDA_S], Al[128*LDA_S];
    __shared__ ushort_t Bh[64*LDBNT_S], Bl[64*LDBNT_S];
    const int bz = blockIdx.z;
    AH += (size_t)bz * sA; AL += (size_t)bz * sA;
    BH += (size_t)bz * sB; BL += (size_t)bz * sB;
    C  += (size_t)bz * sC;
    const int m0 = blockIdx.y * 128, n0 = blockIdx.x * 64;
    const int tid = threadIdx.x, warp = tid >> 5, lane = tid & 31;
    const int wm = (warp >> 1) * 32, wn = (warp & 1) * 32;
    const unsigned baseAh = smem_u32(Ah), baseAl = smem_u32(Al);
    const unsigned baseBh = smem_u32(Bh), baseBl = smem_u32(Bl);

    float c[2][2][2][4];
    #pragma unroll
    for (int a = 0; a < 2; ++a)
        #pragma unroll
        for (int b = 0; b < 2; ++b)
            #pragma unroll
            for (int s = 0; s < 2; ++s)
                #pragma unroll
                for (int q = 0; q < 4; ++q) c[a][b][s][q] = 0.f;

    const int ar = tid >> 1, ac = (tid & 1) * 16;
    const int br = tid >> 2, bc = (tid & 3) * 8;

    for (int kt = 0; kt < K; kt += 32) {
        {   // A tile 128x32 ushorts
            size_t go = (size_t)(m0 + ar) * lda + kt + ac;
            *(uint4*)&Ah[ar * LDA_S + ac]     = *(const uint4*)(AH + go);
            *(uint4*)&Ah[ar * LDA_S + ac + 8] = *(const uint4*)(AH + go + 8);
            *(uint4*)&Al[ar * LDA_S + ac]     = *(const uint4*)(AL + go);
            *(uint4*)&Al[ar * LDA_S + ac + 8] = *(const uint4*)(AL + go + 8);
        }
        {   // B tile 64(n) x 32(k) ushorts
            size_t go = (size_t)(n0 + br) * ldb + kt + bc;
            *(uint4*)&Bh[br * LDBNT_S + bc] = *(const uint4*)(BH + go);
            *(uint4*)&Bl[br * LDBNT_S + bc] = *(const uint4*)(BL + go);
        }
        __syncthreads();
        #pragma unroll
        for (int ks = 0; ks < 2; ++ks) {
            unsigned ah[2][4], al_[2][4];
            #pragma unroll
            for (int mt = 0; mt < 2; ++mt) {
                unsigned off = (unsigned)((wm + mt * 16 + (lane & 15)) * (LDA_S * 2)
                               + ks * 32 + (lane >> 4) * 16);
                ldm_x4(baseAh + off, ah[mt]);
                ldm_x4(baseAl + off, al_[mt]);
            }
            // B fragments via A-style ldmatrix on [n][k] tile:
            // r0=(n0-7,k0-7) r1=(n8-15,k0-7) r2=(n0-7,k8-15) r3=(n8-15,k8-15)
            unsigned bh[2][4], bl_[2][4];
            #pragma unroll
            for (int np = 0; np < 2; ++np) {
                unsigned off = (unsigned)((wn + np * 16 + (lane & 15)) * (LDBNT_S * 2)
                               + ks * 32 + (lane >> 4) * 16);
                ldm_x4(baseBh + off, bh[np]);
                ldm_x4(baseBl + off, bl_[np]);
            }
            #pragma unroll
            for (int mt = 0; mt < 2; ++mt)
                #pragma unroll
                for (int np = 0; np < 2; ++np) {
                    mma_bf16(c[mt][np][0], ah[mt],  bh[np][0],  bh[np][2]);
                    mma_bf16(c[mt][np][1], ah[mt],  bh[np][1],  bh[np][3]);
                    mma_bf16(c[mt][np][0], ah[mt],  bl_[np][0], bl_[np][2]);
                    mma_bf16(c[mt][np][1], ah[mt],  bl_[np][1], bl_[np][3]);
                    mma_bf16(c[mt][np][0], al_[mt], bh[np][0],  bh[np][2]);
                    mma_bf16(c[mt][np][1], al_[mt], bh[np][1],  bh[np][3]);
                }
        }
        __syncthreads();
    }
    const int gq = lane >> 2, tq = lane & 3;
    #pragma unroll
    for (int mt = 0; mt < 2; ++mt)
        #pragma unroll
        for (int np = 0; np < 2; ++np)
            #pragma unroll
            for (int sub = 0; sub < 2; ++sub) {
                int row = m0 + wm + mt * 16 + gq;
                int col = n0 + wn + np * 16 + sub * 8 + tq * 2;
                float* cp = C + (size_t)row * ldc + col;
                *(float2*)cp = make_float2(c[mt][np][sub][0], c[mt][np][sub][1]);
                *(float2*)(cp + (size_t)8 * ldc) = make_float2(c[mt][np][sub][2], c[mt][np][sub][3]);
            }
}

// ---------------- 2D transpose: in[R][C] -> out[C][R] -----------------------
__global__ void transpose2d(const float* __restrict__ in, float* __restrict__ out,
                            int R, int C)
{
    __shared__ float tile[32][33];
    const int c0 = blockIdx.x * 32, r0 = blockIdx.y * 32;
    for (int rr = threadIdx.y; rr < 32; rr += 8) {
        int r = r0 + rr, c = c0 + threadIdx.x;
        if (r < R && c < C) tile[rr][threadIdx.x] = in[(size_t)r * C + c];
    }
    __syncthreads();
    for (int cc = threadIdx.y; cc < 32; cc += 8) {
        int oc = c0 + cc, orw = r0 + threadIdx.x;
        if (oc < C && orw < R) out[(size_t)oc * R + orw] = tile[threadIdx.x][cc];
    }
}

// ---------------- kbw / krb: out[bn*J + j] = bias[n] . vecs[j,b,n,:] ---------
__global__ void bias_dot(const float* __restrict__ vecs, const float* __restrict__ bias,
                         float* __restrict__ out, int J)
{
    int idx = blockIdx.x * blockDim.x + threadIdx.x;
    if (idx >= BN_TOT * J) return;
    int bn = idx / J, j = idx - bn * J;
    int n = bn & 15;
    const float4* v = (const float4*)(vecs + ((size_t)j * BN_TOT + bn) * DHEAD);
    const float4* bp = (const float4*)(bias + n * DHEAD);
    float acc = 0.f;
    #pragma unroll
    for (int d = 0; d < 16; ++d) {
        float4 a = v[d], b = bp[d];
        acc += a.x*b.x + a.y*b.y + a.z*b.z + a.w*b.w;
    }
    out[idx] = acc;
}

// ---------------- efq[i,b,n,s] = (q+r_s_bias) . seg_embed[s,n,:] -------------
__global__ void compute_efq(const float* __restrict__ q, const float* __restrict__ rsb,
                            const float* __restrict__ se,
                            float* __restrict__ e0, float* __restrict__ e1)
{
    int idx = blockIdx.x * blockDim.x + threadIdx.x;   // (i*8+b)*16+n
    if (idx >= QLEN * BN_TOT) return;
    int n = idx & 15;
    const float* qp = q + (size_t)idx * DHEAD;
    const float* rb = rsb + n * DHEAD;
    const float* s0 = se + n * DHEAD;
    const float* s1 = se + (16 + n) * DHEAD;
    float a0 = 0.f, a1 = 0.f;
    #pragma unroll
    for (int d = 0; d < DHEAD; ++d) {
        float qv = qp[d] + rb[d];
        a0 += qv * s0[d];
        a1 += qv * s1[d];
    }
    e0[idx] = a0; e1[idx] = a1;
}

// ---------------- combine scores + softmax; emits P as split bf16 ------------
__global__ void __launch_bounds__(256, 4)
combine_softmax(const float* __restrict__ S1, const float* __restrict__ S2,
                const float* __restrict__ kbw, const float* __restrict__ krb,
                const float* __restrict__ e0a, const float* __restrict__ e1a,
                const float* __restrict__ maskT, const float* __restrict__ segT,
                ushort_t* __restrict__ PH, ushort_t* __restrict__ PL)
{
    const int i = blockIdx.x, bn = blockIdx.y, b = bn >> 4;
    const int tid = threadIdx.x;
    const float* s1row = S1 + ((size_t)bn * QLEN + i) * QLEN;
    const float* s2row = S2 + ((size_t)bn * QLEN + i) * RLEN;
    const float* mrow  = maskT + (size_t)bn * IJ + (size_t)i * QLEN;
    const float* sg0   = segT + (size_t)(b * 2) * IJ + (size_t)i * QLEN;
    const float* sg1   = sg0 + IJ;
    const float* kb = kbw + bn * QLEN;
    const float* kr = krb + bn * RLEN;
    const float e0 = e0a[i * BN_TOT + bn], e1 = e1a[i * BN_TOT + bn];

    float sc[2];
    #pragma unroll
    for (int t = 0; t < 2; ++t) {
        int j = tid + t * 256;
        int p = QLEN - i + j;                    // rel_shift gather, in [1,1023]
        float v = s1row[j] + s2row[p] + kb[j] + kr[p] + sg0[j] * e0 + sg1[j] * e1;
        sc[t] = v * ATT_SCALE - 1e30f * mrow[j];
    }

    const int lane = tid & 31, wid = tid >> 5;
    __shared__ float sred[8];

    float mx = warpMax(fmaxf(sc[0], sc[1]));
    if (lane == 0) sred[wid] = mx;
    __syncthreads();
    if (wid == 0) {
        float v = (lane < 8) ? sred[lane] : -3.0e38f;
        v = warpMax(v);
        if (lane == 0) sred[0] = v;
    }
    __syncthreads();
    mx = sred[0];
    __syncthreads();

    float ex0 = expf(sc[0] - mx), ex1 = expf(sc[1] - mx);
    float s = warpSum(ex0 + ex1);
    if (lane == 0) sred[wid] = s;
    __syncthreads();
    if (wid == 0) {
        float v = (lane < 8) ? sred[lane] : 0.f;
        v = warpSum(v);
        if (lane == 0) sred[0] = v;
    }
    __syncthreads();
    float inv = 1.f / sred[0];
    ushort_t* ph = PH + ((size_t)bn * QLEN + i) * QLEN;
    ushort_t* pl = PL + ((size_t)bn * QLEN + i) * QLEN;
    ushort_t h0, l0, h1, l1;
    split1(ex0 * inv, h0, l0);
    split1(ex1 * inv, h1, l1);
    ph[tid] = h0; pl[tid] = l0;
    ph[tid + 256] = h1; pl[tid + 256] = l1;
}

// ---------------- residual + LayerNorm over last dim (1024) ------------------
__global__ void __launch_bounds__(256, 4)
residual_ln(const float* __restrict__ proj, const float* __restrict__ res,
            const float* __restrict__ gamma, const float* __restrict__ beta,
            float* __restrict__ out)
{
    const int row = blockIdx.x;
    const int tid = threadIdx.x;
    const float* p = proj + (size_t)row * DMODEL;
    const float* r = res  + (size_t)row * DMODEL;
    float x[4];
    float s = 0.f;
    #pragma unroll
    for (int c = 0; c < 4; ++c) {
        int col = tid + c * 256;
        x[c] = p[col] + r[col];
        s += x[c];
    }
    const int lane = tid & 31, wid = tid >> 5;
    __shared__ float sred[8];
    s = warpSum(s);
    if (lane == 0) sred[wid] = s;
    __syncthreads();
    if (wid == 0) {
        float v = (lane < 8) ? sred[lane] : 0.f;
        v = warpSum(v);
        if (lane == 0) sred[0] = v;
    }
    __syncthreads();
    const float mu = sred[0] * (1.f / DMODEL);
    __syncthreads();
    float vs = 0.f;
    #pragma unroll
    for (int c = 0; c < 4; ++c) { float d = x[c] - mu; vs += d * d; }
    vs = warpSum(vs);
    if (lane == 0) sred[wid] = vs;
    __syncthreads();
    if (wid == 0) {
        float v = (lane < 8) ? sred[lane] : 0.f;
        v = warpSum(v);
        if (lane == 0) sred[0] = v;
    }
    __syncthreads();
    const float rs = rsqrtf(sred[0] * (1.f / DMODEL) + 1e-12f);
    float* o = out + (size_t)row * DMODEL;
    #pragma unroll
    for (int c = 0; c < 4; ++c) {
        int col = tid + c * 256;
        o[col] = (x[c] - mu) * rs * gamma[col] + beta[col];
    }
}

// ---------------- launch --------------------------------------------------
extern "C" void kernel_launch(void* const* d_in, const int* in_sizes, int n_in,
                              void* d_out, int out_size)
{
    const float* h       = (const float*)d_in[0];
    const float* g       = (const float*)d_in[1];
    const float* r       = (const float*)d_in[2];
    const float* mask_h  = (const float*)d_in[3];
    const float* mask_g  = (const float*)d_in[4];
    const float* seg_mat = (const float*)d_in[5];
    const float* wq      = (const float*)d_in[6];
    const float* wk      = (const float*)d_in[7];
    const float* wv      = (const float*)d_in[8];
    const float* wo      = (const float*)d_in[9];
    const float* wr      = (const float*)d_in[10];
    const float* rwb     = (const float*)d_in[11];
    const float* rrb     = (const float*)d_in[12];
    const float* rsb     = (const float*)d_in[13];
    const float* se      = (const float*)d_in[14];
    const float* gamma   = (const float*)d_in[15];
    const float* beta    = (const float*)d_in[16];
    float* out = (float*)d_out;

    float *pk, *pv, *pkr, *pq, *pav, *ptmp, *pkbw, *pkrb, *pe0, *pe1,
          *pS1, *pS2, *pmTh, *pmTg, *psegT;
    cudaGetSymbolAddress((void**)&pk,   g_k);
    cudaGetSymbolAddress((void**)&pv,   g_v);
    cudaGetSymbolAddress((void**)&pkr,  g_kr);
    cudaGetSymbolAddress((void**)&pq,   g_q);
    cudaGetSymbolAddress((void**)&pav,  g_av);
    cudaGetSymbolAddress((void**)&ptmp, g_tmp);
    cudaGetSymbolAddress((void**)&pkbw, g_kbw);
    cudaGetSymbolAddress((void**)&pkrb, g_krb);
    cudaGetSymbolAddress((void**)&pe0,  g_e0);
    cudaGetSymbolAddress((void**)&pe1,  g_e1);
    cudaGetSymbolAddress((void**)&pS1,  g_S1);
    cudaGetSymbolAddress((void**)&pS2,  g_S2);
    cudaGetSymbolAddress((void**)&pmTh, g_maskTh);
    cudaGetSymbolAddress((void**)&pmTg, g_maskTg);
    cudaGetSymbolAddress((void**)&psegT, g_segT);

    ushort_t *hH,*hL,*gH,*gL,*rH,*rL,*wqH,*wqL,*wkH,*wkL,*wvH,*wvL,*woH,*woL,
             *wrH,*wrL,*qH,*qL,*kH,*kL,*vH,*vL,*krH,*krL,*PH,*PL,*avH,*avL;
    cudaGetSymbolAddress((void**)&hH, g_hH);   cudaGetSymbolAddress((void**)&hL, g_hL);
    cudaGetSymbolAddress((void**)&gH, g_gH);   cudaGetSymbolAddress((void**)&gL, g_gL);
    cudaGetSymbolAddress((void**)&rH, g_rH);   cudaGetSymbolAddress((void**)&rL, g_rL);
    cudaGetSymbolAddress((void**)&wqH, g_wqH); cudaGetSymbolAddress((void**)&wqL, g_wqL);
    cudaGetSymbolAddress((void**)&wkH, g_wkH); cudaGetSymbolAddress((void**)&wkL, g_wkL);
    cudaGetSymbolAddress((void**)&wvH, g_wvH); cudaGetSymbolAddress((void**)&wvL, g_wvL);
    cudaGetSymbolAddress((void**)&woH, g_woH); cudaGetSymbolAddress((void**)&woL, g_woL);
    cudaGetSymbolAddress((void**)&wrH, g_wrH); cudaGetSymbolAddress((void**)&wrL, g_wrL);
    cudaGetSymbolAddress((void**)&qH, g_qH);   cudaGetSymbolAddress((void**)&qL, g_qL);
    cudaGetSymbolAddress((void**)&kH, g_kH);   cudaGetSymbolAddress((void**)&kL, g_kL);
    cudaGetSymbolAddress((void**)&vH, g_vH);   cudaGetSymbolAddress((void**)&vL, g_vL);
    cudaGetSymbolAddress((void**)&krH, g_krH); cudaGetSymbolAddress((void**)&krL, g_krL);
    cudaGetSymbolAddress((void**)&PH, g_PH);   cudaGetSymbolAddress((void**)&PL, g_PL);
    cudaGetSymbolAddress((void**)&avH, g_avH); cudaGetSymbolAddress((void**)&avL, g_avL);

    #define CVT(src, dh, dl, n) cvt_split<<<((n)/4 + 255)/256, 256>>>(src, dh, dl, (n)/4)

    // ---- one-shot operand conversions ----
    CVT(h, hH, hL, QB*DMODEL);
    CVT(g, gH, gL, QB*DMODEL);
    CVT(r, rH, rL, RB*DMODEL);
    CVT(wq, wqH, wqL, DMODEL*DMODEL);
    CVT(wk, wkH, wkL, DMODEL*DMODEL);
    CVT(wv, wvH, wvL, DMODEL*DMODEL);
    CVT(wo, woH, woL, DMODEL*DMODEL);
    CVT(wr, wrH, wrL, DMODEL*DMODEL);

    // ---- shared precompute ----
    tmma_nn<<<dim3(16, 32, 1), 256>>>(hH, hL, wkH, wkL, pk, DMODEL, DMODEL, DMODEL, DMODEL, 0, 0, 0);
    tmma_nn<<<dim3(16, 32, 1), 256>>>(hH, hL, wvH, wvL, pv, DMODEL, DMODEL, DMODEL, DMODEL, 0, 0, 0);
    tmma_nn<<<dim3(16, 64, 1), 256>>>(rH, rL, wrH, wrL, pkr, DMODEL, DMODEL, DMODEL, DMODEL, 0, 0, 0);
    CVT(pk, kH, kL, QB*DMODEL);
    CVT(pv, vH, vL, QB*DMODEL);
    CVT(pkr, krH, krL, RB*DMODEL);
    bias_dot<<<(BN_TOT * QLEN + 255) / 256, 256>>>(pk,  rwb, pkbw, QLEN);
    bias_dot<<<(BN_TOT * RLEN + 255) / 256, 256>>>(pkr, rrb, pkrb, RLEN);
    transpose2d<<<dim3(4, IJ / 32), dim3(32, 8)>>>(mask_h,  pmTh, IJ, BN_TOT);
    transpose2d<<<dim3(4, IJ / 32), dim3(32, 8)>>>(mask_g,  pmTg, IJ, BN_TOT);
    transpose2d<<<dim3(1, IJ / 32), dim3(32, 8)>>>(seg_mat, psegT, IJ, 16);

    // ---- per-stream pipeline ----
    for (int stream = 0; stream < 2; ++stream) {
        const ushort_t* xH = stream == 0 ? hH : gH;
        const ushort_t* xL = stream == 0 ? hL : gL;
        const float* x = stream == 0 ? h : g;
        const float* mT = stream == 0 ? pmTh : pmTg;
        float* dst = out + (size_t)stream * QB * DMODEL;

        // Q projection
        tmma_nn<<<dim3(16, 32, 1), 256>>>(xH, xL, wqH, wqL, pq, DMODEL, DMODEL, DMODEL, DMODEL, 0, 0, 0);
        compute_efq<<<(QLEN * BN_TOT + 255) / 256, 256>>>(pq, rsb, se, pe0, pe1);
        CVT(pq, qH, qL, QB*DMODEL);
        // S1[bn,i,j] = Q . K^T
        tmma_nt<<<dim3(8, 4, BN_TOT), 256>>>(qH, qL, kH, kL, pS1, DHEAD,
                                             BN_TOT * DHEAD, BN_TOT * DHEAD, QLEN,
                                             DHEAD, DHEAD, (long long)QLEN * QLEN);
        // S2[bn,i,p] = Q . Kr^T
        tmma_nt<<<dim3(16, 4, BN_TOT), 256>>>(qH, qL, krH, krL, pS2, DHEAD,
                                              BN_TOT * DHEAD, BN_TOT * DHEAD, RLEN,
                                              DHEAD, DHEAD, (long long)QLEN * RLEN);
        // scores + softmax -> P (split bf16)
        combine_softmax<<<dim3(QLEN, BN_TOT), 256>>>(pS1, pS2, pkbw, pkrb, pe0, pe1, mT, psegT, PH, PL);
        // attn_vec = P . V
        tmma_nn<<<dim3(1, 4, BN_TOT), 256>>>(PH, PL, vH, vL, pav, QLEN,
                                             QLEN, BN_TOT * DHEAD, BN_TOT * DHEAD,
                                             (long long)QLEN * QLEN, DHEAD, DHEAD);
        CVT(pav, avH, avL, QB*DMODEL);
        // output projection
        tmma_nt<<<dim3(16, 32, 1), 256>>>(avH, avL, woH, woL, ptmp, DMODEL, DMODEL, DMODEL, DMODEL, 0, 0, 0);
        residual_ln<<<QB, 256>>>(ptmp, x, gamma, beta, dst);
    }
    (void)in_sizes; (void)n_in; (void)out_size;
    #undef CVT
}